// round 8
// baseline (speedup 1.0000x reference)
#include <cuda_runtime.h>
#include <cuda_fp16.h>
#include <cstdint>

// Problem: B=2, H=16, S=2048, D=128, temperature=1. Output tuple = (O, attn).
constexpr int kS = 2048;
constexpr int kD = 128;
constexpr int kBH = 32;
constexpr int kQT = 64;             // q rows per CTA
constexpr int kKT = 64;             // keys per tile
constexpr int kTiles = kS / kKT;    // 32
constexpr int kThreads = 256;       // 8 warps: (row-group 0..3) x (half 0..1)
constexpr float kScaleLog2e = 0.08838834764831845f * 1.4426950408889634f;

// smem layout (bytes) — total 88KB -> 2 CTAs/SM
constexpr int SM_Q     = 0;        // 64x128 fp16 (256B/row, 16 chunks, swz ch^(r&7))
constexpr int SM_K     = 16384;    // 64x128 fp16
constexpr int SM_VT    = 32768;    // 128(d) x 64(key) fp16 (128B/row, 8 chunks)
constexpr int SM_P     = 49152;    // 64x64 fp16 (128B/row, 8 chunks)
constexpr int SM_KSTAG = 57344;    // 64x128 fp32 raw K staging (cp.async), 32KB
constexpr int SM_TOTAL = 90112;
// post-loop aliases (P dead then):
constexpr int SM_RSUM = SM_P;          // 128 floats: [half][row]
constexpr int SM_INV  = SM_P + 512;    // 64 floats

__device__ __forceinline__ uint32_t smem_u32(const void* p) {
    uint32_t a;
    asm("{ .reg .u64 t; cvta.to.shared.u64 t, %1; cvt.u32.u64 %0, t; }" : "=r"(a) : "l"(p));
    return a;
}
__device__ __forceinline__ float ex2f(float x) {
    float y; asm("ex2.approx.f32 %0, %1;" : "=f"(y) : "f"(x)); return y;
}

#define CP_ASYNC16(dst, src) \
    asm volatile("cp.async.cg.shared.global [%0], [%1], 16;" :: "r"(dst), "l"(src))
#define CP_COMMIT()  asm volatile("cp.async.commit_group;")
#define CP_WAIT0()   asm volatile("cp.async.wait_group 0;" ::: "memory")

#define LDSM4(r, addr) \
    asm volatile("ldmatrix.sync.aligned.m8n8.x4.shared.b16 {%0,%1,%2,%3}, [%4];" \
        : "=r"((r)[0]), "=r"((r)[1]), "=r"((r)[2]), "=r"((r)[3]) : "r"(addr))

#define MMA(c, a, b0_, b1_) \
    asm volatile("mma.sync.aligned.m16n8k16.row.col.f32.f16.f16.f32 " \
        "{%0,%1,%2,%3}, {%4,%5,%6,%7}, {%8,%9}, {%0,%1,%2,%3};" \
        : "+f"((c)[0]), "+f"((c)[1]), "+f"((c)[2]), "+f"((c)[3]) \
        : "r"((a)[0]), "r"((a)[1]), "r"((a)[2]), "r"((a)[3]), "r"(b0_), "r"(b1_))

// pack 8 floats to 8 fp16 (uint4)
__device__ __forceinline__ uint4 pack8h(const float* v) {
    uint32_t h[4];
    #pragma unroll
    for (int j = 0; j < 4; j++) {
        __half2 t = __floats2half2_rn(v[2 * j], v[2 * j + 1]);
        h[j] = reinterpret_cast<const uint32_t&>(t);
    }
    return make_uint4(h[0], h[1], h[2], h[3]);
}
__device__ __forceinline__ uint32_t pack2h(float a, float b) {
    __half2 t = __floats2half2_rn(a, b);
    return reinterpret_cast<const uint32_t&>(t);
}

// issue cp.async for K tile at key offset k0 into staging (8 x 16B per thread)
__device__ __forceinline__ void cp_k(uint32_t smb, const float* Kg, int k0, int tid) {
    #pragma unroll
    for (int j = 0; j < 8; j++) {
        int idx = j * kThreads + tid;
        int row = idx >> 5, c = idx & 31;   // row 0..63, 16B chunk 0..31
        const float* src = Kg + (size_t)(k0 + row) * kD + c * 4;
        uint32_t dst = smb + SM_KSTAG + row * 512 + ((c ^ (row & 7)) << 4);
        CP_ASYNC16(dst, src);
    }
    CP_COMMIT();
}

__global__ __launch_bounds__(kThreads, 2)
void sdpa_mma_kernel(const float* __restrict__ Q, const float* __restrict__ K,
                     const float* __restrict__ V, const int* __restrict__ mask,
                     float* __restrict__ outO, float* __restrict__ outA) {
    extern __shared__ char sm8[];
    const uint32_t smb = smem_u32(sm8);
    const int tid = threadIdx.x;
    const int wid = tid >> 5, lane = tid & 31;
    const int bh = blockIdx.y;
    const int q0 = blockIdx.x * kQT;
    const int rw = wid & 3, h = wid >> 2;   // row-group / half
    const int r0 = rw * 16;                 // warp's q rows [r0, r0+16)
    const int kh = h * 32;                  // warp's key half (S phase)
    const int g  = lane >> 2;
    const int qt = lane & 3;
    const int lrow = lane & 15, lsel = lane >> 4;

    const float* Qg = Q + ((size_t)bh * kS + q0) * kD;
    const float* Kg = K + (size_t)bh * kS * kD;
    const float* Vg = V + (size_t)bh * kS * kD;

    // ---- prologue: start K0 staging; load Q (prescaled, plain fp16) ----
    cp_k(smb, Kg, 0, tid);
    #pragma unroll
    for (int it = 0; it < 4; it++) {
        int idx = it * kThreads + tid;
        int r = idx >> 4, ch = idx & 15;
        const float* qp = Qg + (size_t)r * kD + ch * 8;
        float v[8];
        #pragma unroll
        for (int j = 0; j < 8; j++) v[j] = qp[j] * kScaleLog2e;
        uint32_t off = (uint32_t)(r * 256 + ((ch ^ (r & 7)) << 4));
        *(uint4*)(sm8 + SM_Q + off) = pack8h(v);
    }

    float oacc[8][4];
    #pragma unroll
    for (int i = 0; i < 8; i++)
        #pragma unroll
        for (int j = 0; j < 4; j++) oacc[i][j] = 0.0f;
    float sum0 = 0.0f, sum1 = 0.0f;

    for (int kt = 0; kt < kTiles; kt++) {
        const int k0 = kt * kKT;

        CP_WAIT0();
        __syncthreads();   // staging ready AND prev tile's reads of K/Vt/P done

        // ---- V tile transposed: gmem fp32 -> Vt[d][key] fp16 smem ----
        #pragma unroll
        for (int it = 0; it < 4; it++) {
            int i = it * kThreads + tid;
            int d = i & 127, kc8 = i >> 7;   // kc8 in 0..7 (8 keys per chunk)
            const float* vp = Vg + (size_t)(k0 + kc8 * 8) * kD + d;
            float v[8];
            #pragma unroll
            for (int j = 0; j < 8; j++) v[j] = vp[(size_t)j * kD];
            uint32_t off = (uint32_t)(d * 128 + ((kc8 ^ (d & 7)) << 4));
            *(uint4*)(sm8 + SM_VT + off) = pack8h(v);
        }
        // ---- K convert: staging raw fp32 -> plain fp16 smem ----
        {
            const int r = tid & 63, grp = tid >> 6;   // grp covers d = grp*32..+31
            float kv[32];
            #pragma unroll
            for (int j = 0; j < 8; j++) {
                uint32_t slot = (uint32_t)(grp * 8 + (j ^ (r & 7)));
                float4 t4 = *(const float4*)(sm8 + SM_KSTAG + r * 512 + slot * 16);
                kv[4 * j + 0] = t4.x; kv[4 * j + 1] = t4.y;
                kv[4 * j + 2] = t4.z; kv[4 * j + 3] = t4.w;
            }
            #pragma unroll
            for (int q = 0; q < 4; q++) {
                int oc = grp * 4 + q;
                uint32_t off = (uint32_t)(r * 256 + ((oc ^ (r & 7)) << 4));
                *(uint4*)(sm8 + SM_K + off) = pack8h(kv + 8 * q);
            }
        }
        __syncthreads();   // K/Vt ready; staging free

        // prefetch next K tile into staging (overlaps compute)
        if (kt + 1 < kTiles) cp_k(smb, Kg, k0 + kKT, tid);

        // hoist mask loads (L2-resident; latency covered by S phase)
        int2 m0r[4], m1r[4];
        {
            const int row_lo = q0 + r0 + g;
            const int cb = k0 + kh + qt * 2;
            const int* m_lo = mask + (size_t)row_lo * kS + cb;
            const int* m_hi = m_lo + (size_t)8 * kS;
            #pragma unroll
            for (int nt = 0; nt < 4; nt++) {
                m0r[nt] = *(const int2*)(m_lo + nt * 8);
                m1r[nt] = *(const int2*)(m_hi + nt * 8);
            }
        }

        // ---- S = Q @ K^T : warp computes 16q x 32keys (pure fp16) ----
        float sacc[4][4];
        #pragma unroll
        for (int i = 0; i < 4; i++)
            #pragma unroll
            for (int j = 0; j < 4; j++) sacc[i][j] = 0.0f;

        #pragma unroll
        for (int c = 0; c < 8; c++) {
            uint32_t af[4];
            {
                int ar = r0 + lrow;
                int ac = 2 * c + lsel;
                uint32_t qa = smb + SM_Q + (uint32_t)(ar * 256 + ((ac ^ (ar & 7)) << 4));
                LDSM4(af, qa);
            }
            #pragma unroll
            for (int np = 0; np < 2; np++) {
                int br = kh + np * 16 + lrow;
                int bc = 2 * c + lsel;
                uint32_t kb = smb + SM_K + (uint32_t)(br * 256 + ((bc ^ (br & 7)) << 4));
                uint32_t bf[4];
                LDSM4(bf, kb);
                MMA(sacc[2 * np],     af, bf[0], bf[2]);
                MMA(sacc[2 * np + 1], af, bf[1], bf[3]);
            }
        }

        // ---- epilogue: mask + ex2, attn out, P fp16 -> smem ----
        {
            const int row_lo = q0 + r0 + g, row_hi = row_lo + 8;
            const int cb = k0 + kh + qt * 2;
            float* a_lo = outA + ((size_t)bh * kS + row_lo) * kS + cb;
            float* a_hi = outA + ((size_t)bh * kS + row_hi) * kS + cb;
            #pragma unroll
            for (int nt = 0; nt < 4; nt++) {
                float p0 = m0r[nt].x ? ex2f(sacc[nt][0]) : 0.0f;
                float p1 = m0r[nt].y ? ex2f(sacc[nt][1]) : 0.0f;
                float p2 = m1r[nt].x ? ex2f(sacc[nt][2]) : 0.0f;
                float p3 = m1r[nt].y ? ex2f(sacc[nt][3]) : 0.0f;
                sum0 += p0 + p1;
                sum1 += p2 + p3;
                *(float2*)(a_lo + nt * 8) = make_float2(p0, p1);
                *(float2*)(a_hi + nt * 8) = make_float2(p2, p3);
                uint32_t h0 = pack2h(p0, p1);
                uint32_t h1 = pack2h(p2, p3);
                uint32_t a0 = smb + SM_P +
                    (uint32_t)((r0 + g) * 128 + (((h * 4 + nt) ^ g) << 4) + 4 * qt);
                asm volatile("st.shared.b32 [%0], %1;" :: "r"(a0), "r"(h0));
                asm volatile("st.shared.b32 [%0], %1;" :: "r"(a0 + 8 * 128), "r"(h1));
            }
        }
        __syncthreads();   // P complete (cross-warp exchange)

        // ---- O += P @ Vt^T : warp computes 16q x 64d (pure fp16) ----
        #pragma unroll
        for (int kc = 0; kc < 4; kc++) {
            uint32_t af[4];
            {
                int ar = r0 + lrow;
                int ac = kc * 2 + lsel;
                uint32_t pa = smb + SM_P + (uint32_t)(ar * 128 + ((ac ^ (ar & 7)) << 4));
                LDSM4(af, pa);
            }
            #pragma unroll
            for (int np = 0; np < 4; np++) {
                int br = h * 64 + np * 16 + lrow;
                int bc = kc * 2 + lsel;
                uint32_t vb = smb + SM_VT + (uint32_t)(br * 128 + ((bc ^ (br & 7)) << 4));
                uint32_t bf[4];
                LDSM4(bf, vb);
                MMA(oacc[2 * np],     af, bf[0], bf[2]);
                MMA(oacc[2 * np + 1], af, bf[1], bf[3]);
            }
        }
    }

    // ---- finalize: rowsums (per key-half partials), combine, normalize ----
    __syncthreads();   // all PV reads of P done; safe to alias RSUM/INV
    sum0 += __shfl_xor_sync(0xffffffffu, sum0, 1);
    sum0 += __shfl_xor_sync(0xffffffffu, sum0, 2);
    sum1 += __shfl_xor_sync(0xffffffffu, sum1, 1);
    sum1 += __shfl_xor_sync(0xffffffffu, sum1, 2);
    float* rsum = (float*)(sm8 + SM_RSUM);
    if (qt == 0) {
        rsum[h * 64 + r0 + g]     = sum0;
        rsum[h * 64 + r0 + g + 8] = sum1;
    }
    __syncthreads();
    float* invp = (float*)(sm8 + SM_INV);
    if (tid < 64) invp[tid] = 1.0f / (rsum[tid] + rsum[64 + tid]);
    __syncthreads();

    const int row_lo = q0 + r0 + g, row_hi = row_lo + 8;
    float inv0 = invp[r0 + g], inv1 = invp[r0 + g + 8];
    float* o_lo = outO + ((size_t)bh * kS + row_lo) * kD + h * 64 + qt * 2;
    float* o_hi = outO + ((size_t)bh * kS + row_hi) * kD + h * 64 + qt * 2;
    #pragma unroll
    for (int nt = 0; nt < 8; nt++) {
        *(float2*)(o_lo + nt * 8) = make_float2(oacc[nt][0] * inv0, oacc[nt][1] * inv0);
        *(float2*)(o_hi + nt * 8) = make_float2(oacc[nt][2] * inv1, oacc[nt][3] * inv1);
    }

    // ---- tail: normalize this CTA's 64-row attn slab ----
    float* abase = outA + ((size_t)bh * kS + q0) * kS;
    #pragma unroll 4
    for (int i = 0; i < 128; i++) {
        int idx = i * kThreads + tid;
        int r = idx >> 9, c = idx & 511;
        float inv = invp[r];
        float4* p = (float4*)(abase + (size_t)r * kS) + c;
        float4 v = *p;
        v.x *= inv; v.y *= inv; v.z *= inv; v.w *= inv;
        *p = v;
    }
}

extern "C" void kernel_launch(void* const* d_in, const int* in_sizes, int n_in,
                              void* d_out, int out_size) {
    const float* Q    = (const float*)d_in[0];
    const float* K    = (const float*)d_in[1];
    const float* V    = (const float*)d_in[2];
    const int*   mask = (const int*)d_in[3];

    float* outO = (float*)d_out;
    float* outA = outO + (size_t)kBH * kS * kD;   // tuple order: (output, attn)

    cudaFuncSetAttribute(sdpa_mma_kernel, cudaFuncAttributeMaxDynamicSharedMemorySize, SM_TOTAL);

    dim3 grid(kS / kQT, kBH);
    sdpa_mma_kernel<<<grid, kThreads, SM_TOTAL>>>(Q, K, V, mask, outO, outA);
}

// round 9
// speedup vs baseline: 1.0197x; 1.0197x over previous
#include <cuda_runtime.h>
#include <cuda_fp16.h>
#include <cstdint>

// Problem: B=2, H=16, S=2048, D=128, temperature=1. Output tuple = (O, attn).
constexpr int kS = 2048;
constexpr int kD = 128;
constexpr int kBH = 32;
constexpr int kQT = 64;             // q rows per CTA
constexpr int kKT = 64;             // keys per tile
constexpr int kTiles = kS / kKT;    // 32
constexpr int kThreads = 256;       // 8 warps: (row-group 0..3) x (half 0..1)
constexpr float kScaleLog2e = 0.08838834764831845f * 1.4426950408889634f;

// smem layout (bytes) — total 104KB -> 2 CTAs/SM
constexpr int SM_K     = 0;        // 64x128 fp16 (256B/row, 16 chunks, swz ch^(r&7))
constexpr int SM_VT    = 16384;    // 128(d) x 64(key) fp16 (128B/row, 8 chunks)
constexpr int SM_P     = 32768;    // 64x64 fp16 (128B/row, 8 chunks)
constexpr int SM_KSTAG = 40960;    // 64x128 fp32 raw K staging (swizzled), 32KB
constexpr int SM_VSTAG = 73728;    // 64x128 fp32 raw V staging (plain), 32KB
constexpr int SM_TOTAL = 106496;
// post-loop aliases (P dead then):
constexpr int SM_RSUM = SM_P;          // 128 floats: [half][row]
constexpr int SM_INV  = SM_P + 512;    // 64 floats

__device__ __forceinline__ uint32_t smem_u32(const void* p) {
    uint32_t a;
    asm("{ .reg .u64 t; cvta.to.shared.u64 t, %1; cvt.u32.u64 %0, t; }" : "=r"(a) : "l"(p));
    return a;
}
__device__ __forceinline__ float ex2f(float x) {
    float y; asm("ex2.approx.f32 %0, %1;" : "=f"(y) : "f"(x)); return y;
}

#define CP_ASYNC16(dst, src) \
    asm volatile("cp.async.cg.shared.global [%0], [%1], 16;" :: "r"(dst), "l"(src))
#define CP_COMMIT()  asm volatile("cp.async.commit_group;")
#define CP_WAIT0()   asm volatile("cp.async.wait_group 0;" ::: "memory")

#define LDSM4(r, addr) \
    asm volatile("ldmatrix.sync.aligned.m8n8.x4.shared.b16 {%0,%1,%2,%3}, [%4];" \
        : "=r"((r)[0]), "=r"((r)[1]), "=r"((r)[2]), "=r"((r)[3]) : "r"(addr))

#define MMA(c, a, b0_, b1_) \
    asm volatile("mma.sync.aligned.m16n8k16.row.col.f32.f16.f16.f32 " \
        "{%0,%1,%2,%3}, {%4,%5,%6,%7}, {%8,%9}, {%0,%1,%2,%3};" \
        : "+f"((c)[0]), "+f"((c)[1]), "+f"((c)[2]), "+f"((c)[3]) \
        : "r"((a)[0]), "r"((a)[1]), "r"((a)[2]), "r"((a)[3]), "r"(b0_), "r"(b1_))

// pack 8 floats to 8 fp16 (uint4)
__device__ __forceinline__ uint4 pack8h(const float* v) {
    uint32_t h[4];
    #pragma unroll
    for (int j = 0; j < 4; j++) {
        __half2 t = __floats2half2_rn(v[2 * j], v[2 * j + 1]);
        h[j] = reinterpret_cast<const uint32_t&>(t);
    }
    return make_uint4(h[0], h[1], h[2], h[3]);
}
__device__ __forceinline__ uint32_t pack2h(float a, float b) {
    __half2 t = __floats2half2_rn(a, b);
    return reinterpret_cast<const uint32_t&>(t);
}

// issue cp.async for K and V tiles at key offset k0 into staging; one commit group
__device__ __forceinline__ void cp_kv(uint32_t smb, const float* Kg, const float* Vg,
                                      int k0, int tid) {
    #pragma unroll
    for (int j = 0; j < 8; j++) {
        int idx = j * kThreads + tid;
        int row = idx >> 5, c = idx & 31;   // row 0..63, 16B chunk 0..31
        CP_ASYNC16(smb + SM_KSTAG + row * 512 + ((c ^ (row & 7)) << 4),
                   Kg + (size_t)(k0 + row) * kD + c * 4);
    }
    #pragma unroll
    for (int j = 0; j < 8; j++) {
        int idx = j * kThreads + tid;
        int row = idx >> 5, c = idx & 31;
        CP_ASYNC16(smb + SM_VSTAG + row * 512 + c * 16,
                   Vg + (size_t)(k0 + row) * kD + c * 4);
    }
    CP_COMMIT();
}

__global__ __launch_bounds__(kThreads, 2)
void sdpa_mma_kernel(const float* __restrict__ Q, const float* __restrict__ K,
                     const float* __restrict__ V, const int* __restrict__ mask,
                     float* __restrict__ outO, float* __restrict__ outA) {
    extern __shared__ char sm8[];
    const uint32_t smb = smem_u32(sm8);
    const int tid = threadIdx.x;
    const int wid = tid >> 5, lane = tid & 31;
    const int bh = blockIdx.y;
    const int q0 = blockIdx.x * kQT;
    const int rw = wid & 3, h = wid >> 2;   // row-group / half
    const int r0 = rw * 16;                 // warp's q rows [r0, r0+16)
    const int kh = h * 32;                  // warp's key half (S phase)
    const int g  = lane >> 2;
    const int qt = lane & 3;
    const int lrow = lane & 15, lsel = lane >> 4;

    const float* Qg = Q + ((size_t)bh * kS + q0) * kD;
    const float* Kg = K + (size_t)bh * kS * kD;
    const float* Vg = V + (size_t)bh * kS * kD;

    // ---- prologue: start K0/V0 staging; load Q A-fragments into registers ----
    cp_kv(smb, Kg, Vg, 0, tid);

    // m16n8k16 A-fragment layout per chunk c (k = 16c..16c+15):
    //   qf[c][0]=(row g,   k-lo) qf[c][1]=(row g+8, k-lo)
    //   qf[c][2]=(row g,   k-hi) qf[c][3]=(row g+8, k-hi)
    uint32_t qf[8][4];
    {
        const float* qr0 = Qg + (size_t)(r0 + g) * kD;
        const float* qr1 = qr0 + 8 * kD;
        #pragma unroll
        for (int c = 0; c < 8; c++) {
            float2 a0 = *(const float2*)(qr0 + 16 * c + 2 * qt);
            float2 a1 = *(const float2*)(qr1 + 16 * c + 2 * qt);
            float2 a2 = *(const float2*)(qr0 + 16 * c + 8 + 2 * qt);
            float2 a3 = *(const float2*)(qr1 + 16 * c + 8 + 2 * qt);
            qf[c][0] = pack2h(a0.x * kScaleLog2e, a0.y * kScaleLog2e);
            qf[c][1] = pack2h(a1.x * kScaleLog2e, a1.y * kScaleLog2e);
            qf[c][2] = pack2h(a2.x * kScaleLog2e, a2.y * kScaleLog2e);
            qf[c][3] = pack2h(a3.x * kScaleLog2e, a3.y * kScaleLog2e);
        }
    }

    float oacc[8][4];
    #pragma unroll
    for (int i = 0; i < 8; i++)
        #pragma unroll
        for (int j = 0; j < 4; j++) oacc[i][j] = 0.0f;
    float sum0 = 0.0f, sum1 = 0.0f;

    for (int kt = 0; kt < kTiles; kt++) {
        const int k0 = kt * kKT;

        CP_WAIT0();
        __syncthreads();   // staging ready AND prev tile's reads of K/Vt/P done

        // ---- K convert: staging (swz fp32) -> plain fp16 smem ----
        {
            const int r = tid & 63, grp = tid >> 6;   // grp covers d = grp*32..+31
            float kv[32];
            #pragma unroll
            for (int j = 0; j < 8; j++) {
                uint32_t slot = (uint32_t)(grp * 8 + (j ^ (r & 7)));
                float4 t4 = *(const float4*)(sm8 + SM_KSTAG + r * 512 + slot * 16);
                kv[4 * j + 0] = t4.x; kv[4 * j + 1] = t4.y;
                kv[4 * j + 2] = t4.z; kv[4 * j + 3] = t4.w;
            }
            #pragma unroll
            for (int q = 0; q < 4; q++) {
                int oc = grp * 4 + q;
                uint32_t off = (uint32_t)(r * 256 + ((oc ^ (r & 7)) << 4));
                *(uint4*)(sm8 + SM_K + off) = pack8h(kv + 8 * q);
            }
        }
        // ---- V convert with transpose: staging [key][d] fp32 -> Vt[d][key] fp16 ----
        {
            float vv[32];   // vv[m*8+j] = V[8*wid + j][lane + 32*m]
            #pragma unroll
            for (int m = 0; m < 4; m++)
                #pragma unroll
                for (int j = 0; j < 8; j++)
                    vv[m * 8 + j] = *(const float*)(sm8 + SM_VSTAG +
                        (8 * wid + j) * 512 + (lane + 32 * m) * 4);
            #pragma unroll
            for (int m = 0; m < 4; m++) {
                int d = lane + 32 * m;
                uint32_t off = (uint32_t)(d * 128 + ((wid ^ (d & 7)) << 4));
                *(uint4*)(sm8 + SM_VT + off) = pack8h(vv + m * 8);
            }
        }
        __syncthreads();   // K/Vt ready; staging free

        // prefetch next K/V tiles into staging (covered by full tile of compute)
        if (kt + 1 < kTiles) cp_kv(smb, Kg, Vg, k0 + kKT, tid);

        // hoist mask loads (L2-resident; latency covered by S phase)
        int2 m0r[4], m1r[4];
        {
            const int row_lo = q0 + r0 + g;
            const int cb = k0 + kh + qt * 2;
            const int* m_lo = mask + (size_t)row_lo * kS + cb;
            const int* m_hi = m_lo + (size_t)8 * kS;
            #pragma unroll
            for (int nt = 0; nt < 4; nt++) {
                m0r[nt] = *(const int2*)(m_lo + nt * 8);
                m1r[nt] = *(const int2*)(m_hi + nt * 8);
            }
        }

        // ---- S = Q @ K^T : warp computes 16q x 32keys (Q from registers) ----
        float sacc[4][4];
        #pragma unroll
        for (int i = 0; i < 4; i++)
            #pragma unroll
            for (int j = 0; j < 4; j++) sacc[i][j] = 0.0f;

        #pragma unroll
        for (int c = 0; c < 8; c++) {
            #pragma unroll
            for (int np = 0; np < 2; np++) {
                int br = kh + np * 16 + lrow;
                int bc = 2 * c + lsel;
                uint32_t kb = smb + SM_K + (uint32_t)(br * 256 + ((bc ^ (br & 7)) << 4));
                uint32_t bf[4];
                LDSM4(bf, kb);
                MMA(sacc[2 * np],     qf[c], bf[0], bf[2]);
                MMA(sacc[2 * np + 1], qf[c], bf[1], bf[3]);
            }
        }

        // ---- epilogue: mask + ex2, attn out, P fp16 -> smem ----
        {
            const int row_lo = q0 + r0 + g, row_hi = row_lo + 8;
            const int cb = k0 + kh + qt * 2;
            float* a_lo = outA + ((size_t)bh * kS + row_lo) * kS + cb;
            float* a_hi = outA + ((size_t)bh * kS + row_hi) * kS + cb;
            #pragma unroll
            for (int nt = 0; nt < 4; nt++) {
                float p0 = m0r[nt].x ? ex2f(sacc[nt][0]) : 0.0f;
                float p1 = m0r[nt].y ? ex2f(sacc[nt][1]) : 0.0f;
                float p2 = m1r[nt].x ? ex2f(sacc[nt][2]) : 0.0f;
                float p3 = m1r[nt].y ? ex2f(sacc[nt][3]) : 0.0f;
                sum0 += p0 + p1;
                sum1 += p2 + p3;
                *(float2*)(a_lo + nt * 8) = make_float2(p0, p1);
                *(float2*)(a_hi + nt * 8) = make_float2(p2, p3);
                uint32_t h0 = pack2h(p0, p1);
                uint32_t h1 = pack2h(p2, p3);
                uint32_t a0 = smb + SM_P +
                    (uint32_t)((r0 + g) * 128 + (((h * 4 + nt) ^ g) << 4) + 4 * qt);
                asm volatile("st.shared.b32 [%0], %1;" :: "r"(a0), "r"(h0));
                asm volatile("st.shared.b32 [%0], %1;" :: "r"(a0 + 8 * 128), "r"(h1));
            }
        }
        __syncthreads();   // P complete (cross-warp exchange)

        // ---- O += P @ Vt^T : warp computes 16q x 64d ----
        #pragma unroll
        for (int kc = 0; kc < 4; kc++) {
            uint32_t af[4];
            {
                int ar = r0 + lrow;
                int ac = kc * 2 + lsel;
                uint32_t pa = smb + SM_P + (uint32_t)(ar * 128 + ((ac ^ (ar & 7)) << 4));
                LDSM4(af, pa);
            }
            #pragma unroll
            for (int np = 0; np < 4; np++) {
                int br = h * 64 + np * 16 + lrow;
                int bc = kc * 2 + lsel;
                uint32_t vb = smb + SM_VT + (uint32_t)(br * 128 + ((bc ^ (br & 7)) << 4));
                uint32_t bf[4];
                LDSM4(bf, vb);
                MMA(oacc[2 * np],     af, bf[0], bf[2]);
                MMA(oacc[2 * np + 1], af, bf[1], bf[3]);
            }
        }
    }

    // ---- finalize: rowsums (per key-half partials), combine, normalize ----
    __syncthreads();   // all PV reads of P done; safe to alias RSUM/INV
    sum0 += __shfl_xor_sync(0xffffffffu, sum0, 1);
    sum0 += __shfl_xor_sync(0xffffffffu, sum0, 2);
    sum1 += __shfl_xor_sync(0xffffffffu, sum1, 1);
    sum1 += __shfl_xor_sync(0xffffffffu, sum1, 2);
    float* rsum = (float*)(sm8 + SM_RSUM);
    if (qt == 0) {
        rsum[h * 64 + r0 + g]     = sum0;
        rsum[h * 64 + r0 + g + 8] = sum1;
    }
    __syncthreads();
    float* invp = (float*)(sm8 + SM_INV);
    if (tid < 64) invp[tid] = 1.0f / (rsum[tid] + rsum[64 + tid]);
    __syncthreads();

    const int row_lo = q0 + r0 + g, row_hi = row_lo + 8;
    float inv0 = invp[r0 + g], inv1 = invp[r0 + g + 8];
    float* o_lo = outO + ((size_t)bh * kS + row_lo) * kD + h * 64 + qt * 2;
    float* o_hi = outO + ((size_t)bh * kS + row_hi) * kD + h * 64 + qt * 2;
    #pragma unroll
    for (int nt = 0; nt < 8; nt++) {
        *(float2*)(o_lo + nt * 8) = make_float2(oacc[nt][0] * inv0, oacc[nt][1] * inv0);
        *(float2*)(o_hi + nt * 8) = make_float2(oacc[nt][2] * inv1, oacc[nt][3] * inv1);
    }

    // ---- tail: normalize this CTA's 64-row attn slab ----
    float* abase = outA + ((size_t)bh * kS + q0) * kS;
    #pragma unroll 4
    for (int i = 0; i < 128; i++) {
        int idx = i * kThreads + tid;
        int r = idx >> 9, c = idx & 511;
        float inv = invp[r];
        float4* p = (float4*)(abase + (size_t)r * kS) + c;
        float4 v = *p;
        v.x *= inv; v.y *= inv; v.z *= inv; v.w *= inv;
        *p = v;
    }
}

extern "C" void kernel_launch(void* const* d_in, const int* in_sizes, int n_in,
                              void* d_out, int out_size) {
    const float* Q    = (const float*)d_in[0];
    const float* K    = (const float*)d_in[1];
    const float* V    = (const float*)d_in[2];
    const int*   mask = (const int*)d_in[3];

    float* outO = (float*)d_out;
    float* outA = outO + (size_t)kBH * kS * kD;   // tuple order: (output, attn)

    cudaFuncSetAttribute(sdpa_mma_kernel, cudaFuncAttributeMaxDynamicSharedMemorySize, SM_TOTAL);

    dim3 grid(kS / kQT, kBH);
    sdpa_mma_kernel<<<grid, kThreads, SM_TOTAL>>>(Q, K, V, mask, outO, outA);
}